// round 12
// baseline (speedup 1.0000x reference)
#include <cuda_runtime.h>
#include <cuda_fp16.h>
#include <cstdint>
#include <math.h>

#define BB 4
#define TT 16
#define SS 256
#define DD 1024
#define HH 16
#define HKV 4
#define HD 64
#define NSEQ (BB*TT)
#define NROWS (NSEQ*SS)
#define N_IMG 240

__device__ float g_Q[NROWS * DD];
__device__ float g_K[NROWS * HKV * HD];
__device__ float g_V[NROWS * HKV * HD];
__device__ float g_AO[NROWS * DD];
__device__ float g_X[NROWS * DD];          // tf32-rounded x
__device__ float g_Wqr[DD * DD];           // tf32-rounded weights
__device__ float g_Wkr[DD * HKV * HD];
__device__ float g_Wvr[DD * HKV * HD];
__device__ float g_Wor[DD * DD];

// ---------------------------------------------------------------------------
__device__ __forceinline__ float to_tf32(float x) {
    float y; asm("cvt.rna.tf32.f32 %0, %1;" : "=f"(y) : "f"(x)); return y;
}
__device__ __forceinline__ void mma_tf32(float* d, const uint32_t* a, const uint32_t* b) {
    asm volatile(
        "mma.sync.aligned.m16n8k8.row.col.f32.tf32.tf32.f32 "
        "{%0,%1,%2,%3}, {%4,%5,%6,%7}, {%8,%9}, {%0,%1,%2,%3};"
        : "+f"(d[0]), "+f"(d[1]), "+f"(d[2]), "+f"(d[3])
        : "r"(a[0]), "r"(a[1]), "r"(a[2]), "r"(a[3]), "r"(b[0]), "r"(b[1]));
}
__device__ __forceinline__ void mma_f16(float* d, const uint32_t* a, uint32_t b0, uint32_t b1) {
    asm volatile(
        "mma.sync.aligned.m16n8k16.row.col.f32.f16.f16.f32 "
        "{%0,%1,%2,%3}, {%4,%5,%6,%7}, {%8,%9}, {%0,%1,%2,%3};"
        : "+f"(d[0]), "+f"(d[1]), "+f"(d[2]), "+f"(d[3])
        : "r"(a[0]), "r"(a[1]), "r"(a[2]), "r"(a[3]), "r"(b0), "r"(b1));
}
__device__ __forceinline__ uint32_t pack_h2(float a, float b) {
    __half2 h = __floats2half2_rn(a, b);
    return *reinterpret_cast<uint32_t*>(&h);
}
__device__ __forceinline__ uint32_t cvta_smem(const void* p) {
    uint32_t a;
    asm("{ .reg .u64 t; cvta.to.shared.u64 t, %1; cvt.u32.u64 %0, t; }"
        : "=r"(a) : "l"(p));
    return a;
}
#define CP_ASYNC16(dst_u32, src_ptr) \
    asm volatile("cp.async.ca.shared.global [%0], [%1], 16;" \
                 :: "r"(dst_u32), "l"(src_ptr) : "memory")
#define CP_COMMIT() asm volatile("cp.async.commit_group;" ::: "memory")
#define CP_WAIT3()  asm volatile("cp.async.wait_group 3;" ::: "memory")

// ---------------------------------------------------------------------------
// tf32-RNA rounding pass
// ---------------------------------------------------------------------------
__global__ __launch_bounds__(256) void round_tf32_kernel(
    const float4* __restrict__ src, float4* __restrict__ dst, int n4)
{
    int i = blockIdx.x * 256 + threadIdx.x;
    if (i < n4) {
        float4 v = src[i];
        dst[i] = make_float4(to_tf32(v.x), to_tf32(v.y), to_tf32(v.z), to_tf32(v.w));
    }
}

// ---------------------------------------------------------------------------
// TF32 GEMM, 4-stage cp.async pipeline, 512 threads, tile 128x128,
// warp tile 32x32 (16 warps, 4x4). Inputs PRE-ROUNDED to tf32.
// ---------------------------------------------------------------------------
#define A_STRIDE 36
#define B_STRIDE 136
#define A_SZ (128 * A_STRIDE)
#define B_SZ (32 * B_STRIDE)
#define NSTAGE 4
#define GEMM_SMEM ((NSTAGE * (A_SZ + B_SZ)) * (int)sizeof(float))  // 143360 B

__device__ __forceinline__ void gemm_body(
    const float* __restrict__ A, const float* __restrict__ W,
    float* __restrict__ C, int N, int K, int m0, int n0, float* sm)
{
    float* As[NSTAGE];
    float* Bs[NSTAGE];
    uint32_t asu[NSTAGE], bsu[NSTAGE];
    const uint32_t sb = cvta_smem(sm);
    #pragma unroll
    for (int s = 0; s < NSTAGE; s++) {
        As[s] = sm + s * (A_SZ + B_SZ);
        Bs[s] = As[s] + A_SZ;
        asu[s] = sb + s * (A_SZ + B_SZ) * 4;
        bsu[s] = asu[s] + A_SZ * 4;
    }

    const int tid  = threadIdx.x;
    const int wid  = tid >> 5;
    const int lane = tid & 31;
    const int grp  = lane >> 2;
    const int tig  = lane & 3;
    const int m_off = (wid & 3) * 32;
    const int n_off = (wid >> 2) * 32;

    float acc[2][4][4];
    #pragma unroll
    for (int mt = 0; mt < 2; mt++)
        #pragma unroll
        for (int nt = 0; nt < 4; nt++)
            #pragma unroll
            for (int i = 0; i < 4; i++) acc[mt][nt][i] = 0.f;

    const int KT = K >> 5;

    // stage(kt, buf): A 1024 f4 + B 1024 f4 over 512 threads = 2+2 per thread
    #define STAGE(kt, b) do {                                               \
        const int kn_ = (kt) * 32;                                          \
        _Pragma("unroll")                                                   \
        for (int s_ = 0; s_ < 2; s_++) {                                    \
            int c_ = tid + s_ * 512;                                        \
            int am_ = c_ >> 3, k4_ = c_ & 7;                                \
            CP_ASYNC16(asu[b] + am_ * (A_STRIDE * 4) + k4_ * 16,            \
                       A + (size_t)(m0 + am_) * K + kn_ + k4_ * 4);         \
            int bk_ = c_ >> 5, bn4_ = c_ & 31;                              \
            CP_ASYNC16(bsu[b] + bk_ * (B_STRIDE * 4) + bn4_ * 16,           \
                       W + (size_t)(kn_ + bk_) * N + n0 + bn4_ * 4);        \
        }                                                                   \
    } while (0)

    STAGE(0, 0); CP_COMMIT();
    STAGE(1, 1); CP_COMMIT();
    STAGE(2, 2); CP_COMMIT();

    for (int kt = 0; kt < KT; kt++) {
        if (kt + 3 < KT) STAGE(kt + 3, (kt + 3) & 3);
        CP_COMMIT();
        CP_WAIT3();
        __syncthreads();

        float* Ab = As[kt & 3];
        float* Bb = Bs[kt & 3];
        #pragma unroll
        for (int ks = 0; ks < 4; ks++) {
            const int k = ks * 8;
            uint32_t af[2][4], bf[4][2];
            #pragma unroll
            for (int mt = 0; mt < 2; mt++) {
                const int row = m_off + mt * 16 + grp;
                af[mt][0] = __float_as_uint(Ab[row * A_STRIDE + k + tig]);
                af[mt][1] = __float_as_uint(Ab[(row + 8) * A_STRIDE + k + tig]);
                af[mt][2] = __float_as_uint(Ab[row * A_STRIDE + k + tig + 4]);
                af[mt][3] = __float_as_uint(Ab[(row + 8) * A_STRIDE + k + tig + 4]);
            }
            #pragma unroll
            for (int nt = 0; nt < 4; nt++) {
                const int col = n_off + nt * 8 + grp;
                bf[nt][0] = __float_as_uint(Bb[(k + tig) * B_STRIDE + col]);
                bf[nt][1] = __float_as_uint(Bb[(k + tig + 4) * B_STRIDE + col]);
            }
            #pragma unroll
            for (int mt = 0; mt < 2; mt++)
                #pragma unroll
                for (int nt = 0; nt < 4; nt++)
                    mma_tf32(acc[mt][nt], af[mt], bf[nt]);
        }
        __syncthreads();
    }
    #undef STAGE

    #pragma unroll
    for (int mt = 0; mt < 2; mt++) {
        const int row = m0 + m_off + mt * 16 + grp;
        #pragma unroll
        for (int nt = 0; nt < 4; nt++) {
            const int col = n0 + n_off + nt * 8 + 2 * tig;
            *(float2*)(C + (size_t)row * N + col) =
                make_float2(acc[mt][nt][0], acc[mt][nt][1]);
            *(float2*)(C + (size_t)(row + 8) * N + col) =
                make_float2(acc[mt][nt][2], acc[mt][nt][3]);
        }
    }
}

// Fused QKV: blockIdx.x 0-7 -> Q cols, 8-9 -> K, 10-11 -> V
__global__ __launch_bounds__(512) void gemm_qkv(
    const float* __restrict__ A, const float* __restrict__ Wq,
    const float* __restrict__ Wk, const float* __restrict__ Wv)
{
    extern __shared__ float sm[];
    const int ct = blockIdx.x;
    const float* W; float* C; int N, n0;
    if (ct < 8)       { W = Wq; C = g_Q; N = DD;       n0 = ct * 128; }
    else if (ct < 10) { W = Wk; C = g_K; N = HKV * HD; n0 = (ct - 8) * 128; }
    else              { W = Wv; C = g_V; N = HKV * HD; n0 = (ct - 10) * 128; }
    gemm_body(A, W, C, N, DD, blockIdx.y * 128, n0, sm);
}

__global__ __launch_bounds__(512) void gemm_mma_tf32(
    const float* __restrict__ A, const float* __restrict__ W,
    float* __restrict__ C, int N, int K)
{
    extern __shared__ float sm[];
    gemm_body(A, W, C, N, K, blockIdx.y * 128, blockIdx.x * 128, sm);
}

// ---------------------------------------------------------------------------
// RMSNorm + RoPE (unchanged)
// ---------------------------------------------------------------------------
__global__ __launch_bounds__(256) void normrope_kernel(
    const float* __restrict__ rope_cos, const float* __restrict__ rope_sin,
    const float* __restrict__ q_scale, const float* __restrict__ k_scale)
{
    const int w    = blockIdx.x * 8 + (threadIdx.x >> 5);
    const int lane = threadIdx.x & 31;

    float* ptr; const float* sc; int s;
    const int NQ = NROWS * HH;
    if (w < NQ) {
        int ns = w >> 4, h = w & 15;
        ptr = g_Q + (size_t)ns * DD + h * HD;
        s = ns & (SS - 1); sc = q_scale;
    } else {
        int r = w - NQ, ns = r >> 2, hk = r & 3;
        ptr = g_K + (size_t)ns * (HKV * HD) + hk * HD;
        s = ns & (SS - 1); sc = k_scale;
    }

    float a = ptr[lane];
    float b = ptr[lane + 32];
    float ssq = a * a + b * b;
    #pragma unroll
    for (int off = 16; off > 0; off >>= 1)
        ssq += __shfl_xor_sync(0xFFFFFFFFu, ssq, off);
    float r = rsqrtf(ssq * (1.0f / 64.0f) + 1e-6f);

    float an = a * r * sc[lane];
    float bn = b * r * sc[lane + 32];
    float c  = rope_cos[s * 32 + lane];
    float sn = rope_sin[s * 32 + lane];
    ptr[lane]      = an * c - bn * sn;
    ptr[lane + 32] = bn * c + an * sn;
}

// ---------------------------------------------------------------------------
// Flash attention, f16 mma (writes tf32-rounded AO).
// ---------------------------------------------------------------------------
#define QP_STR 36
#define VT_STR 132
#define ATTN_SMEM ((512 * QP_STR + 64 * VT_STR) * 4)   // 107520 B

__global__ __launch_bounds__(256) void attn_mma(
    const float* __restrict__ Q, const float* __restrict__ Kg,
    const float* __restrict__ Vg, float* __restrict__ O)
{
    extern __shared__ uint32_t smu[];
    uint32_t* Qp = smu;
    uint32_t* Kp = smu + 256 * QP_STR;
    uint32_t* Vt = smu + 512 * QP_STR;

    const int blk = blockIdx.x;
    const int n = blk >> 4, hk = (blk >> 2) & 3, qq = blk & 3;
    const int tid = threadIdx.x, w = tid >> 5, lane = tid & 31;
    const int grp = lane >> 2, tig = lane & 3;

    #pragma unroll
    for (int i = 0; i < 16; i++) {
        int flat = tid + i * 256;
        int hrow = flat >> 4, c4 = flat & 15;
        int head = hrow >> 6, row = hrow & 63;
        float4 v = *(const float4*)(
            Q + (size_t)(n * SS + qq * 64 + row) * DD + (hk * 4 + head) * HD + c4 * 4);
        Qp[hrow * QP_STR + c4 * 2]     = pack_h2(v.x, v.y);
        Qp[hrow * QP_STR + c4 * 2 + 1] = pack_h2(v.z, v.w);
    }
    #pragma unroll
    for (int i = 0; i < 16; i++) {
        int flat = tid + i * 256;
        int row = flat >> 4, c4 = flat & 15;
        float4 v = *(const float4*)(
            Kg + (size_t)(n * SS + row) * (HKV * HD) + hk * HD + c4 * 4);
        Kp[row * QP_STR + c4 * 2]     = pack_h2(v.x, v.y);
        Kp[row * QP_STR + c4 * 2 + 1] = pack_h2(v.z, v.w);
    }
    #pragma unroll
    for (int i = 0; i < 32; i++) {
        int flat = tid + i * 256;
        int hd = flat & 63, kp = flat >> 6;
        const float* vp = Vg + (size_t)(n * SS + 2 * kp) * (HKV * HD) + hk * HD + hd;
        Vt[hd * VT_STR + kp] = pack_h2(vp[0], vp[HKV * HD]);
    }
    __syncthreads();

    const int qbase = (w >> 1) * 64 + (w & 1) * 32;
    const int qrow0 = qq * 64 + (w & 1) * 32;

    float o[2][8][4];
    #pragma unroll
    for (int mt = 0; mt < 2; mt++)
        #pragma unroll
        for (int nt = 0; nt < 8; nt++)
            #pragma unroll
            for (int e = 0; e < 4; e++) o[mt][nt][e] = 0.f;
    float m_run[2][2] = {{-1e30f,-1e30f},{-1e30f,-1e30f}};
    float l_run[2][2] = {{0.f,0.f},{0.f,0.f}};

    for (int c = 0; c < 4; c++) {
        float s[2][8][4];
        #pragma unroll
        for (int mt = 0; mt < 2; mt++)
            #pragma unroll
            for (int nt = 0; nt < 8; nt++)
                #pragma unroll
                for (int e = 0; e < 4; e++) s[mt][nt][e] = 0.f;

        #pragma unroll
        for (int ks = 0; ks < 4; ks++) {
            uint32_t a[2][4];
            #pragma unroll
            for (int mt = 0; mt < 2; mt++) {
                int r = qbase + mt * 16 + grp;
                a[mt][0] = Qp[r * QP_STR + 8 * ks + tig];
                a[mt][1] = Qp[(r + 8) * QP_STR + 8 * ks + tig];
                a[mt][2] = Qp[r * QP_STR + 8 * ks + tig + 4];
                a[mt][3] = Qp[(r + 8) * QP_STR + 8 * ks + tig + 4];
            }
            #pragma unroll
            for (int nt = 0; nt < 8; nt++) {
                int kr = c * 64 + nt * 8 + grp;
                uint32_t b0 = Kp[kr * QP_STR + 8 * ks + tig];
                uint32_t b1 = Kp[kr * QP_STR + 8 * ks + tig + 4];
                #pragma unroll
                for (int mt = 0; mt < 2; mt++) mma_f16(s[mt][nt], a[mt], b0, b1);
            }
        }

        #pragma unroll
        for (int mt = 0; mt < 2; mt++) {
            #pragma unroll
            for (int half = 0; half < 2; half++) {
                int qrow = qrow0 + mt * 16 + grp + half * 8;
                float sv[8][2];
                float mx = -1e30f;
                #pragma unroll
                for (int nt = 0; nt < 8; nt++) {
                    #pragma unroll
                    for (int e2 = 0; e2 < 2; e2++) {
                        int kcol = c * 64 + nt * 8 + 2 * tig + e2;
                        float d = s[mt][nt][half * 2 + e2] * 0.125f;
                        float ex = __expf(d * 0.04f);
                        float t = 50.f - 100.f / (ex + 1.f);
                        bool masked = (qrow < N_IMG) && (kcol >= N_IMG);
                        sv[nt][e2] = masked ? -1e30f : t;
                        mx = fmaxf(mx, sv[nt][e2]);
                    }
                }
                mx = fmaxf(mx, __shfl_xor_sync(0xFFFFFFFFu, mx, 1));
                mx = fmaxf(mx, __shfl_xor_sync(0xFFFFFFFFu, mx, 2));
                float m_new = fmaxf(m_run[mt][half], mx);
                float corr = __expf(m_run[mt][half] - m_new);
                m_run[mt][half] = m_new;
                float lsum = 0.f;
                #pragma unroll
                for (int nt = 0; nt < 8; nt++) {
                    #pragma unroll
                    for (int e2 = 0; e2 < 2; e2++) {
                        float p = __expf(sv[nt][e2] - m_new);
                        s[mt][nt][half * 2 + e2] = p;
                        lsum += p;
                    }
                }
                lsum += __shfl_xor_sync(0xFFFFFFFFu, lsum, 1);
                lsum += __shfl_xor_sync(0xFFFFFFFFu, lsum, 2);
                l_run[mt][half] = l_run[mt][half] * corr + lsum;
                #pragma unroll
                for (int nt = 0; nt < 8; nt++) {
                    o[mt][nt][half * 2]     *= corr;
                    o[mt][nt][half * 2 + 1] *= corr;
                }
            }
        }

        #pragma unroll
        for (int ks = 0; ks < 4; ks++) {
            uint32_t a[2][4];
            #pragma unroll
            for (int mt = 0; mt < 2; mt++) {
                a[mt][0] = pack_h2(s[mt][2 * ks][0],     s[mt][2 * ks][1]);
                a[mt][1] = pack_h2(s[mt][2 * ks][2],     s[mt][2 * ks][3]);
                a[mt][2] = pack_h2(s[mt][2 * ks + 1][0], s[mt][2 * ks + 1][1]);
                a[mt][3] = pack_h2(s[mt][2 * ks + 1][2], s[mt][2 * ks + 1][3]);
            }
            #pragma unroll
            for (int nt = 0; nt < 8; nt++) {
                int hd = nt * 8 + grp;
                uint32_t b0 = Vt[hd * VT_STR + c * 32 + 8 * ks + tig];
                uint32_t b1 = Vt[hd * VT_STR + c * 32 + 8 * ks + tig + 4];
                #pragma unroll
                for (int mt = 0; mt < 2; mt++) mma_f16(o[mt][nt], a[mt], b0, b1);
            }
        }
    }

    const int head = hk * 4 + (w >> 1);
    #pragma unroll
    for (int mt = 0; mt < 2; mt++) {
        int r0 = qrow0 + mt * 16 + grp;
        #pragma unroll
        for (int half = 0; half < 2; half++) {
            float inv = 1.f / l_run[mt][half];
            float* op = O + (size_t)(n * SS + r0 + half * 8) * DD + head * HD;
            #pragma unroll
            for (int nt = 0; nt < 8; nt++)
                *(float2*)(op + nt * 8 + 2 * tig) = make_float2(
                    to_tf32(o[mt][nt][half * 2] * inv),
                    to_tf32(o[mt][nt][half * 2 + 1] * inv));
        }
    }
}

// ---------------------------------------------------------------------------
extern "C" void kernel_launch(void* const* d_in, const int* in_sizes, int n_in,
                              void* d_out, int out_size)
{
    const float* x        = (const float*)d_in[0];
    const float* rope_cos = (const float*)d_in[2];
    const float* rope_sin = (const float*)d_in[3];
    const float* Wq       = (const float*)d_in[4];
    const float* Wk       = (const float*)d_in[5];
    const float* Wv       = (const float*)d_in[6];
    const float* Wo       = (const float*)d_in[7];
    const float* q_scale  = (const float*)d_in[8];
    const float* k_scale  = (const float*)d_in[9];
    float* out = (float*)d_out;

    float *pQ, *pK, *pV, *pAO, *pX, *pWq, *pWk, *pWv, *pWo;
    cudaGetSymbolAddress((void**)&pQ,  g_Q);
    cudaGetSymbolAddress((void**)&pK,  g_K);
    cudaGetSymbolAddress((void**)&pV,  g_V);
    cudaGetSymbolAddress((void**)&pAO, g_AO);
    cudaGetSymbolAddress((void**)&pX,  g_X);
    cudaGetSymbolAddress((void**)&pWq, g_Wqr);
    cudaGetSymbolAddress((void**)&pWk, g_Wkr);
    cudaGetSymbolAddress((void**)&pWv, g_Wvr);
    cudaGetSymbolAddress((void**)&pWo, g_Wor);

    cudaFuncSetAttribute(gemm_qkv, cudaFuncAttributeMaxDynamicSharedMemorySize, GEMM_SMEM);
    cudaFuncSetAttribute(gemm_mma_tf32, cudaFuncAttributeMaxDynamicSharedMemorySize, GEMM_SMEM);
    cudaFuncSetAttribute(attn_mma, cudaFuncAttributeMaxDynamicSharedMemorySize, ATTN_SMEM);

    // 0) Pre-round inputs/weights to tf32 (RNA)
    round_tf32_kernel<<<(NROWS * DD / 4 + 255) / 256, 256>>>((const float4*)x, (float4*)pX, NROWS * DD / 4);
    round_tf32_kernel<<<(DD * DD / 4 + 255) / 256, 256>>>((const float4*)Wq, (float4*)pWq, DD * DD / 4);
    round_tf32_kernel<<<(DD * HKV * HD / 4 + 255) / 256, 256>>>((const float4*)Wk, (float4*)pWk, DD * HKV * HD / 4);
    round_tf32_kernel<<<(DD * HKV * HD / 4 + 255) / 256, 256>>>((const float4*)Wv, (float4*)pWv, DD * HKV * HD / 4);
    round_tf32_kernel<<<(DD * DD / 4 + 255) / 256, 256>>>((const float4*)Wo, (float4*)pWo, DD * DD / 4);

    // 1) Fused Q/K/V projections
    gemm_qkv<<<dim3(12, NROWS / 128), 512, GEMM_SMEM>>>(pX, pWq, pWk, pWv);

    // 2) RMSNorm + RoPE
    normrope_kernel<<<(NROWS * HH + NROWS * HKV) / 8, 256>>>(rope_cos, rope_sin,
                                                             q_scale, k_scale);

    // 3) Flash attention (f16 mma); writes tf32-rounded AO
    attn_mma<<<NSEQ * HKV * 4, 256, ATTN_SMEM>>>(pQ, pK, pV, pAO);

    // 4) Output projection
    gemm_mma_tf32<<<dim3(DD / 128, NROWS / 128), 512, GEMM_SMEM>>>(pAO, pWo, out, DD, DD);
}

// round 14
// speedup vs baseline: 1.2166x; 1.2166x over previous
#include <cuda_runtime.h>
#include <cuda_fp16.h>
#include <cstdint>
#include <math.h>

#define BB 4
#define TT 16
#define SS 256
#define DD 1024
#define HH 16
#define HKV 4
#define HD 64
#define NSEQ (BB*TT)
#define NROWS (NSEQ*SS)
#define N_IMG 240

__device__ float g_Q[NROWS * DD];
__device__ float g_K[NROWS * HKV * HD];
__device__ float g_V[NROWS * HKV * HD];
__device__ float g_AO[NROWS * DD];
__device__ float g_X[NROWS * DD];          // tf32-rounded x
__device__ float g_Wqr[DD * DD];           // tf32-rounded weights
__device__ float g_Wkr[DD * HKV * HD];
__device__ float g_Wvr[DD * HKV * HD];
__device__ float g_Wor[DD * DD];

// ---------------------------------------------------------------------------
__device__ __forceinline__ float to_tf32(float x) {
    float y; asm("cvt.rna.tf32.f32 %0, %1;" : "=f"(y) : "f"(x)); return y;
}
__device__ __forceinline__ void mma_tf32(float* d, const uint32_t* a, const uint32_t* b) {
    asm volatile(
        "mma.sync.aligned.m16n8k8.row.col.f32.tf32.tf32.f32 "
        "{%0,%1,%2,%3}, {%4,%5,%6,%7}, {%8,%9}, {%0,%1,%2,%3};"
        : "+f"(d[0]), "+f"(d[1]), "+f"(d[2]), "+f"(d[3])
        : "r"(a[0]), "r"(a[1]), "r"(a[2]), "r"(a[3]), "r"(b[0]), "r"(b[1]));
}
__device__ __forceinline__ void mma_f16(float* d, const uint32_t* a, uint32_t b0, uint32_t b1) {
    asm volatile(
        "mma.sync.aligned.m16n8k16.row.col.f32.f16.f16.f32 "
        "{%0,%1,%2,%3}, {%4,%5,%6,%7}, {%8,%9}, {%0,%1,%2,%3};"
        : "+f"(d[0]), "+f"(d[1]), "+f"(d[2]), "+f"(d[3])
        : "r"(a[0]), "r"(a[1]), "r"(a[2]), "r"(a[3]), "r"(b0), "r"(b1));
}
__device__ __forceinline__ uint32_t pack_h2(float a, float b) {
    __half2 h = __floats2half2_rn(a, b);
    return *reinterpret_cast<uint32_t*>(&h);
}
__device__ __forceinline__ uint32_t cvta_smem(const void* p) {
    uint32_t a;
    asm("{ .reg .u64 t; cvta.to.shared.u64 t, %1; cvt.u32.u64 %0, t; }"
        : "=r"(a) : "l"(p));
    return a;
}
#define CP_ASYNC16(dst_u32, src_ptr) \
    asm volatile("cp.async.cg.shared.global [%0], [%1], 16;" \
                 :: "r"(dst_u32), "l"(src_ptr) : "memory")
#define CP_COMMIT() asm volatile("cp.async.commit_group;" ::: "memory")
#define CP_WAIT1()  asm volatile("cp.async.wait_group 1;" ::: "memory")

// ---------------------------------------------------------------------------
// tf32-RNA rounding pass
// ---------------------------------------------------------------------------
__global__ __launch_bounds__(256) void round_tf32_kernel(
    const float4* __restrict__ src, float4* __restrict__ dst, int n4)
{
    int i = blockIdx.x * 256 + threadIdx.x;
    if (i < n4) {
        float4 v = src[i];
        dst[i] = make_float4(to_tf32(v.x), to_tf32(v.y), to_tf32(v.z), to_tf32(v.w));
    }
}

// ---------------------------------------------------------------------------
// TF32 GEMM, 3-stage cp.async pipeline, ONE __syncthreads per chunk.
// 512 threads, tile 128x128, warp tile 32x32. Inputs PRE-ROUNDED to tf32.
// ---------------------------------------------------------------------------
#define A_STRIDE 36
#define B_STRIDE 136
#define A_SZ (128 * A_STRIDE)
#define B_SZ (32 * B_STRIDE)
#define NSTAGE 3
#define GEMM_SMEM ((NSTAGE * (A_SZ + B_SZ)) * (int)sizeof(float))  // 107520 B

__device__ __forceinline__ void gemm_body(
    const float* __restrict__ A, const float* __restrict__ W,
    float* __restrict__ C, int N, int K, int m0, int n0, float* sm)
{
    float* As[NSTAGE];
    float* Bs[NSTAGE];
    uint32_t asu[NSTAGE], bsu[NSTAGE];
    const uint32_t sb = cvta_smem(sm);
    #pragma unroll
    for (int s = 0; s < NSTAGE; s++) {
        As[s] = sm + s * (A_SZ + B_SZ);
        Bs[s] = As[s] + A_SZ;
        asu[s] = sb + s * (A_SZ + B_SZ) * 4;
        bsu[s] = asu[s] + A_SZ * 4;
    }

    const int tid  = threadIdx.x;
    const int wid  = tid >> 5;
    const int lane = tid & 31;
    const int grp  = lane >> 2;
    const int tig  = lane & 3;
    const int m_off = (wid & 3) * 32;
    const int n_off = (wid >> 2) * 32;

    float acc[2][4][4];
    #pragma unroll
    for (int mt = 0; mt < 2; mt++)
        #pragma unroll
        for (int nt = 0; nt < 4; nt++)
            #pragma unroll
            for (int i = 0; i < 4; i++) acc[mt][nt][i] = 0.f;

    const int KT = K >> 5;

    // stage(kt, buf): A 1024 f4 + B 1024 f4 over 512 threads = 2+2 per thread
    #define STAGE(kt, b) do {                                               \
        const int kn_ = (kt) * 32;                                          \
        _Pragma("unroll")                                                   \
        for (int s_ = 0; s_ < 2; s_++) {                                    \
            int c_ = tid + s_ * 512;                                        \
            int am_ = c_ >> 3, k4_ = c_ & 7;                                \
            CP_ASYNC16(asu[b] + am_ * (A_STRIDE * 4) + k4_ * 16,            \
                       A + (size_t)(m0 + am_) * K + kn_ + k4_ * 4);         \
            int bk_ = c_ >> 5, bn4_ = c_ & 31;                              \
            CP_ASYNC16(bsu[b] + bk_ * (B_STRIDE * 4) + bn4_ * 16,           \
                       W + (size_t)(kn_ + bk_) * N + n0 + bn4_ * 4);        \
        }                                                                   \
    } while (0)

    // Prologue: stages 0 and 1 in flight; wait for stage 0.
    STAGE(0, 0); CP_COMMIT();
    STAGE(1, 1); CP_COMMIT();
    CP_WAIT1();
    __syncthreads();

    int cur = 0;   // compute buffer = kt % 3
    int stg = 2;   // stage buffer   = (kt + 2) % 3
    for (int kt = 0; kt < KT; kt++) {
        float* Ab = As[cur];
        float* Bb = Bs[cur];

        #pragma unroll
        for (int ks = 0; ks < 4; ks++) {
            const int k = ks * 8;
            uint32_t af[2][4], bf[4][2];
            #pragma unroll
            for (int mt = 0; mt < 2; mt++) {
                const int row = m_off + mt * 16 + grp;
                af[mt][0] = __float_as_uint(Ab[row * A_STRIDE + k + tig]);
                af[mt][1] = __float_as_uint(Ab[(row + 8) * A_STRIDE + k + tig]);
                af[mt][2] = __float_as_uint(Ab[row * A_STRIDE + k + tig + 4]);
                af[mt][3] = __float_as_uint(Ab[(row + 8) * A_STRIDE + k + tig + 4]);
            }
            #pragma unroll
            for (int nt = 0; nt < 4; nt++) {
                const int col = n_off + nt * 8 + grp;
                bf[nt][0] = __float_as_uint(Bb[(k + tig) * B_STRIDE + col]);
                bf[nt][1] = __float_as_uint(Bb[(k + tig + 4) * B_STRIDE + col]);
            }
            #pragma unroll
            for (int mt = 0; mt < 2; mt++)
                #pragma unroll
                for (int nt = 0; nt < 4; nt++)
                    mma_tf32(acc[mt][nt], af[mt], bf[nt]);

            // Mid-chunk: issue next-next stage (buffer (kt-1)%3 -- its readers
            // all passed the trailing sync of iteration kt-1; race-free).
            if (ks == 1) {
                if (kt + 2 < KT) STAGE(kt + 2, stg);
                CP_COMMIT();
            }
        }

        CP_WAIT1();          // stage kt+1 resident before next chunk
        __syncthreads();     // single barrier per chunk

        cur = (cur == 2) ? 0 : cur + 1;
        stg = (stg == 2) ? 0 : stg + 1;
    }
    #undef STAGE

    #pragma unroll
    for (int mt = 0; mt < 2; mt++) {
        const int row = m0 + m_off + mt * 16 + grp;
        #pragma unroll
        for (int nt = 0; nt < 4; nt++) {
            const int col = n0 + n_off + nt * 8 + 2 * tig;
            *(float2*)(C + (size_t)row * N + col) =
                make_float2(acc[mt][nt][0], acc[mt][nt][1]);
            *(float2*)(C + (size_t)(row + 8) * N + col) =
                make_float2(acc[mt][nt][2], acc[mt][nt][3]);
        }
    }
}

// Fused QKV: blockIdx.x 0-7 -> Q cols, 8-9 -> K, 10-11 -> V
__global__ __launch_bounds__(512) void gemm_qkv(
    const float* __restrict__ A, const float* __restrict__ Wq,
    const float* __restrict__ Wk, const float* __restrict__ Wv)
{
    extern __shared__ float sm[];
    const int ct = blockIdx.x;
    const float* W; float* C; int N, n0;
    if (ct < 8)       { W = Wq; C = g_Q; N = DD;       n0 = ct * 128; }
    else if (ct < 10) { W = Wk; C = g_K; N = HKV * HD; n0 = (ct - 8) * 128; }
    else              { W = Wv; C = g_V; N = HKV * HD; n0 = (ct - 10) * 128; }
    gemm_body(A, W, C, N, DD, blockIdx.y * 128, n0, sm);
}

__global__ __launch_bounds__(512) void gemm_mma_tf32(
    const float* __restrict__ A, const float* __restrict__ W,
    float* __restrict__ C, int N, int K)
{
    extern __shared__ float sm[];
    gemm_body(A, W, C, N, K, blockIdx.y * 128, blockIdx.x * 128, sm);
}

// ---------------------------------------------------------------------------
// RMSNorm + RoPE (unchanged)
// ---------------------------------------------------------------------------
__global__ __launch_bounds__(256) void normrope_kernel(
    const float* __restrict__ rope_cos, const float* __restrict__ rope_sin,
    const float* __restrict__ q_scale, const float* __restrict__ k_scale)
{
    const int w    = blockIdx.x * 8 + (threadIdx.x >> 5);
    const int lane = threadIdx.x & 31;

    float* ptr; const float* sc; int s;
    const int NQ = NROWS * HH;
    if (w < NQ) {
        int ns = w >> 4, h = w & 15;
        ptr = g_Q + (size_t)ns * DD + h * HD;
        s = ns & (SS - 1); sc = q_scale;
    } else {
        int r = w - NQ, ns = r >> 2, hk = r & 3;
        ptr = g_K + (size_t)ns * (HKV * HD) + hk * HD;
        s = ns & (SS - 1); sc = k_scale;
    }

    float a = ptr[lane];
    float b = ptr[lane + 32];
    float ssq = a * a + b * b;
    #pragma unroll
    for (int off = 16; off > 0; off >>= 1)
        ssq += __shfl_xor_sync(0xFFFFFFFFu, ssq, off);
    float r = rsqrtf(ssq * (1.0f / 64.0f) + 1e-6f);

    float an = a * r * sc[lane];
    float bn = b * r * sc[lane + 32];
    float c  = rope_cos[s * 32 + lane];
    float sn = rope_sin[s * 32 + lane];
    ptr[lane]      = an * c - bn * sn;
    ptr[lane + 32] = bn * c + an * sn;
}

// ---------------------------------------------------------------------------
// Flash attention, f16 mma (writes tf32-rounded AO).
// ---------------------------------------------------------------------------
#define QP_STR 36
#define VT_STR 132
#define ATTN_SMEM ((512 * QP_STR + 64 * VT_STR) * 4)   // 107520 B

__global__ __launch_bounds__(256) void attn_mma(
    const float* __restrict__ Q, const float* __restrict__ Kg,
    const float* __restrict__ Vg, float* __restrict__ O)
{
    extern __shared__ uint32_t smu[];
    uint32_t* Qp = smu;
    uint32_t* Kp = smu + 256 * QP_STR;
    uint32_t* Vt = smu + 512 * QP_STR;

    const int blk = blockIdx.x;
    const int n = blk >> 4, hk = (blk >> 2) & 3, qq = blk & 3;
    const int tid = threadIdx.x, w = tid >> 5, lane = tid & 31;
    const int grp = lane >> 2, tig = lane & 3;

    #pragma unroll
    for (int i = 0; i < 16; i++) {
        int flat = tid + i * 256;
        int hrow = flat >> 4, c4 = flat & 15;
        int head = hrow >> 6, row = hrow & 63;
        float4 v = *(const float4*)(
            Q + (size_t)(n * SS + qq * 64 + row) * DD + (hk * 4 + head) * HD + c4 * 4);
        Qp[hrow * QP_STR + c4 * 2]     = pack_h2(v.x, v.y);
        Qp[hrow * QP_STR + c4 * 2 + 1] = pack_h2(v.z, v.w);
    }
    #pragma unroll
    for (int i = 0; i < 16; i++) {
        int flat = tid + i * 256;
        int row = flat >> 4, c4 = flat & 15;
        float4 v = *(const float4*)(
            Kg + (size_t)(n * SS + row) * (HKV * HD) + hk * HD + c4 * 4);
        Kp[row * QP_STR + c4 * 2]     = pack_h2(v.x, v.y);
        Kp[row * QP_STR + c4 * 2 + 1] = pack_h2(v.z, v.w);
    }
    #pragma unroll
    for (int i = 0; i < 32; i++) {
        int flat = tid + i * 256;
        int hd = flat & 63, kp = flat >> 6;
        const float* vp = Vg + (size_t)(n * SS + 2 * kp) * (HKV * HD) + hk * HD + hd;
        Vt[hd * VT_STR + kp] = pack_h2(vp[0], vp[HKV * HD]);
    }
    __syncthreads();

    const int qbase = (w >> 1) * 64 + (w & 1) * 32;
    const int qrow0 = qq * 64 + (w & 1) * 32;

    float o[2][8][4];
    #pragma unroll
    for (int mt = 0; mt < 2; mt++)
        #pragma unroll
        for (int nt = 0; nt < 8; nt++)
            #pragma unroll
            for (int e = 0; e < 4; e++) o[mt][nt][e] = 0.f;
    float m_run[2][2] = {{-1e30f,-1e30f},{-1e30f,-1e30f}};
    float l_run[2][2] = {{0.f,0.f},{0.f,0.f}};

    for (int c = 0; c < 4; c++) {
        float s[2][8][4];
        #pragma unroll
        for (int mt = 0; mt < 2; mt++)
            #pragma unroll
            for (int nt = 0; nt < 8; nt++)
                #pragma unroll
                for (int e = 0; e < 4; e++) s[mt][nt][e] = 0.f;

        #pragma unroll
        for (int ks = 0; ks < 4; ks++) {
            uint32_t a[2][4];
            #pragma unroll
            for (int mt = 0; mt < 2; mt++) {
                int r = qbase + mt * 16 + grp;
                a[mt][0] = Qp[r * QP_STR + 8 * ks + tig];
                a[mt][1] = Qp[(r + 8) * QP_STR + 8 * ks + tig];
                a[mt][2] = Qp[r * QP_STR + 8 * ks + tig + 4];
                a[mt][3] = Qp[(r + 8) * QP_STR + 8 * ks + tig + 4];
            }
            #pragma unroll
            for (int nt = 0; nt < 8; nt++) {
                int kr = c * 64 + nt * 8 + grp;
                uint32_t b0 = Kp[kr * QP_STR + 8 * ks + tig];
                uint32_t b1 = Kp[kr * QP_STR + 8 * ks + tig + 4];
                #pragma unroll
                for (int mt = 0; mt < 2; mt++) mma_f16(s[mt][nt], a[mt], b0, b1);
            }
        }

        #pragma unroll
        for (int mt = 0; mt < 2; mt++) {
            #pragma unroll
            for (int half = 0; half < 2; half++) {
                int qrow = qrow0 + mt * 16 + grp + half * 8;
                float sv[8][2];
                float mx = -1e30f;
                #pragma unroll
                for (int nt = 0; nt < 8; nt++) {
                    #pragma unroll
                    for (int e2 = 0; e2 < 2; e2++) {
                        int kcol = c * 64 + nt * 8 + 2 * tig + e2;
                        float d = s[mt][nt][half * 2 + e2] * 0.125f;
                        float ex = __expf(d * 0.04f);
                        float t = 50.f - 100.f / (ex + 1.f);
                        bool masked = (qrow < N_IMG) && (kcol >= N_IMG);
                        sv[nt][e2] = masked ? -1e30f : t;
                        mx = fmaxf(mx, sv[nt][e2]);
                    }
                }
                mx = fmaxf(mx, __shfl_xor_sync(0xFFFFFFFFu, mx, 1));
                mx = fmaxf(mx, __shfl_xor_sync(0xFFFFFFFFu, mx, 2));
                float m_new = fmaxf(m_run[mt][half], mx);
                float corr = __expf(m_run[mt][half] - m_new);
                m_run[mt][half] = m_new;
                float lsum = 0.f;
                #pragma unroll
                for (int nt = 0; nt < 8; nt++) {
                    #pragma unroll
                    for (int e2 = 0; e2 < 2; e2++) {
                        float p = __expf(sv[nt][e2] - m_new);
                        s[mt][nt][half * 2 + e2] = p;
                        lsum += p;
                    }
                }
                lsum += __shfl_xor_sync(0xFFFFFFFFu, lsum, 1);
                lsum += __shfl_xor_sync(0xFFFFFFFFu, lsum, 2);
                l_run[mt][half] = l_run[mt][half] * corr + lsum;
                #pragma unroll
                for (int nt = 0; nt < 8; nt++) {
                    o[mt][nt][half * 2]     *= corr;
                    o[mt][nt][half * 2 + 1] *= corr;
                }
            }
        }

        #pragma unroll
        for (int ks = 0; ks < 4; ks++) {
            uint32_t a[2][4];
            #pragma unroll
            for (int mt = 0; mt < 2; mt++) {
                a[mt][0] = pack_h2(s[mt][2 * ks][0],     s[mt][2 * ks][1]);
                a[mt][1] = pack_h2(s[mt][2 * ks][2],     s[mt][2 * ks][3]);
                a[mt][2] = pack_h2(s[mt][2 * ks + 1][0], s[mt][2 * ks + 1][1]);
                a[mt][3] = pack_h2(s[mt][2 * ks + 1][2], s[mt][2 * ks + 1][3]);
            }
            #pragma unroll
            for (int nt = 0; nt < 8; nt++) {
                int hd = nt * 8 + grp;
                uint32_t b0 = Vt[hd * VT_STR + c * 32 + 8 * ks + tig];
                uint32_t b1 = Vt[hd * VT_STR + c * 32 + 8 * ks + tig + 4];
                #pragma unroll
                for (int mt = 0; mt < 2; mt++) mma_f16(o[mt][nt], a[mt], b0, b1);
            }
        }
    }

    const int head = hk * 4 + (w >> 1);
    #pragma unroll
    for (int mt = 0; mt < 2; mt++) {
        int r0 = qrow0 + mt * 16 + grp;
        #pragma unroll
        for (int half = 0; half < 2; half++) {
            float inv = 1.f / l_run[mt][half];
            float* op = O + (size_t)(n * SS + r0 + half * 8) * DD + head * HD;
            #pragma unroll
            for (int nt = 0; nt < 8; nt++)
                *(float2*)(op + nt * 8 + 2 * tig) = make_float2(
                    to_tf32(o[mt][nt][half * 2] * inv),
                    to_tf32(o[mt][nt][half * 2 + 1] * inv));
        }
    }
}

// ---------------------------------------------------------------------------
extern "C" void kernel_launch(void* const* d_in, const int* in_sizes, int n_in,
                              void* d_out, int out_size)
{
    const float* x        = (const float*)d_in[0];
    const float* rope_cos = (const float*)d_in[2];
    const float* rope_sin = (const float*)d_in[3];
    const float* Wq       = (const float*)d_in[4];
    const float* Wk       = (const float*)d_in[5];
    const float* Wv       = (const float*)d_in[6];
    const float* Wo       = (const float*)d_in[7];
    const float* q_scale  = (const float*)d_in[8];
    const float* k_scale  = (const float*)d_in[9];
    float* out = (float*)d_out;

    float *pQ, *pK, *pV, *pAO, *pX, *pWq, *pWk, *pWv, *pWo;
    cudaGetSymbolAddress((void**)&pQ,  g_Q);
    cudaGetSymbolAddress((void**)&pK,  g_K);
    cudaGetSymbolAddress((void**)&pV,  g_V);
    cudaGetSymbolAddress((void**)&pAO, g_AO);
    cudaGetSymbolAddress((void**)&pX,  g_X);
    cudaGetSymbolAddress((void**)&pWq, g_Wqr);
    cudaGetSymbolAddress((void**)&pWk, g_Wkr);
    cudaGetSymbolAddress((void**)&pWv, g_Wvr);
    cudaGetSymbolAddress((void**)&pWo, g_Wor);

    cudaFuncSetAttribute(gemm_qkv, cudaFuncAttributeMaxDynamicSharedMemorySize, GEMM_SMEM);
    cudaFuncSetAttribute(gemm_mma_tf32, cudaFuncAttributeMaxDynamicSharedMemorySize, GEMM_SMEM);
    cudaFuncSetAttribute(attn_mma, cudaFuncAttributeMaxDynamicSharedMemorySize, ATTN_SMEM);

    // 0) Pre-round inputs/weights to tf32 (RNA)
    round_tf32_kernel<<<(NROWS * DD / 4 + 255) / 256, 256>>>((const float4*)x, (float4*)pX, NROWS * DD / 4);
    round_tf32_kernel<<<(DD * DD / 4 + 255) / 256, 256>>>((const float4*)Wq, (float4*)pWq, DD * DD / 4);
    round_tf32_kernel<<<(DD * HKV * HD / 4 + 255) / 256, 256>>>((const float4*)Wk, (float4*)pWk, DD * HKV * HD / 4);
    round_tf32_kernel<<<(DD * HKV * HD / 4 + 255) / 256, 256>>>((const float4*)Wv, (float4*)pWv, DD * HKV * HD / 4);
    round_tf32_kernel<<<(DD * DD / 4 + 255) / 256, 256>>>((const float4*)Wo, (float4*)pWo, DD * DD / 4);

    // 1) Fused Q/K/V projections
    gemm_qkv<<<dim3(12, NROWS / 128), 512, GEMM_SMEM>>>(pX, pWq, pWk, pWv);

    // 2) RMSNorm + RoPE
    normrope_kernel<<<(NROWS * HH + NROWS * HKV) / 8, 256>>>(rope_cos, rope_sin,
                                                             q_scale, k_scale);

    // 3) Flash attention (f16 mma); writes tf32-rounded AO
    attn_mma<<<NSEQ * HKV * 4, 256, ATTN_SMEM>>>(pQ, pK, pV, pAO);

    // 4) Output projection
    gemm_mma_tf32<<<dim3(DD / 128, NROWS / 128), 512, GEMM_SMEM>>>(pAO, pWo, out, DD, DD);
}

// round 15
// speedup vs baseline: 1.7974x; 1.4774x over previous
#include <cuda_runtime.h>
#include <cuda_fp16.h>
#include <cstdint>
#include <math.h>

#define BB 4
#define TT 16
#define SS 256
#define DD 1024
#define HH 16
#define HKV 4
#define HD 64
#define NSEQ (BB*TT)
#define NROWS (NSEQ*SS)
#define N_IMG 240

__device__ float  g_Q[NROWS * DD];
__device__ float  g_K[NROWS * HKV * HD];
__device__ float  g_V[NROWS * HKV * HD];
__device__ __half g_Xh[NROWS * DD];        // f16 x
__device__ __half g_AOh[NROWS * DD];       // f16 attention output
__device__ __half g_Wqt[DD * DD];          // f16 W^T: [N][K]
__device__ __half g_Wkt[HKV * HD * DD];
__device__ __half g_Wvt[HKV * HD * DD];
__device__ __half g_Wot[DD * DD];

// ---------------------------------------------------------------------------
__device__ __forceinline__ void mma_f16(float* d, const uint32_t* a, uint32_t b0, uint32_t b1) {
    asm volatile(
        "mma.sync.aligned.m16n8k16.row.col.f32.f16.f16.f32 "
        "{%0,%1,%2,%3}, {%4,%5,%6,%7}, {%8,%9}, {%0,%1,%2,%3};"
        : "+f"(d[0]), "+f"(d[1]), "+f"(d[2]), "+f"(d[3])
        : "r"(a[0]), "r"(a[1]), "r"(a[2]), "r"(a[3]), "r"(b0), "r"(b1));
}
__device__ __forceinline__ uint32_t pack_h2(float a, float b) {
    __half2 h = __floats2half2_rn(a, b);
    return *reinterpret_cast<uint32_t*>(&h);
}
__device__ __forceinline__ uint32_t cvta_smem(const void* p) {
    uint32_t a;
    asm("{ .reg .u64 t; cvta.to.shared.u64 t, %1; cvt.u32.u64 %0, t; }"
        : "=r"(a) : "l"(p));
    return a;
}
#define CP_ASYNC16(dst_u32, src_ptr) \
    asm volatile("cp.async.cg.shared.global [%0], [%1], 16;" \
                 :: "r"(dst_u32), "l"(src_ptr) : "memory")
#define CP_COMMIT() asm volatile("cp.async.commit_group;" ::: "memory")
#define CP_WAIT1()  asm volatile("cp.async.wait_group 1;" ::: "memory")

// ---------------------------------------------------------------------------
// f32 -> f16 convert (elementwise)
// ---------------------------------------------------------------------------
__global__ __launch_bounds__(256) void f32_to_f16_kernel(
    const float4* __restrict__ src, uint2* __restrict__ dst, int n4)
{
    int i = blockIdx.x * 256 + threadIdx.x;
    if (i < n4) {
        float4 v = src[i];
        dst[i] = make_uint2(pack_h2(v.x, v.y), pack_h2(v.z, v.w));
    }
}

// ---------------------------------------------------------------------------
// Convert + transpose: Wt[n][k] (f16) = W[k][n] (f32)
// ---------------------------------------------------------------------------
__global__ __launch_bounds__(256) void transpose_f16_kernel(
    const float* __restrict__ W, __half* __restrict__ Wt, int K, int N)
{
    __shared__ __half t[32][33];
    const int n0 = blockIdx.x * 32, k0 = blockIdx.y * 32;
    const int x = threadIdx.x, y = threadIdx.y;
    #pragma unroll
    for (int r = 0; r < 32; r += 8)
        t[y + r][x] = __float2half_rn(W[(size_t)(k0 + y + r) * N + n0 + x]);
    __syncthreads();
    #pragma unroll
    for (int r = 0; r < 32; r += 8)
        Wt[(size_t)(n0 + y + r) * K + k0 + x] = t[x][y + r];
}

// ---------------------------------------------------------------------------
// F16 GEMM: C[M,N](f32) = A[M,K](f16) * Wt[N,K](f16)^T
// 3-stage cp.async pipeline, ONE sync per chunk, 512 threads,
// tile 128x128, BK=32, warp tile 32x32 (m16n8k16).
// Smem rows padded to 20 u32 (conflict-free for (grp,tig) fragment reads).
// ---------------------------------------------------------------------------
#define R_STR 20                          // u32 per smem row (16 payload + 4 pad)
#define CH_SZ (128 * R_STR)               // u32 per A (or B) chunk
#define NSTAGE 3
#define GEMM_SMEM (NSTAGE * 2 * CH_SZ * 4)   // 61440 B

__device__ __forceinline__ void gemm_body_f16(
    const __half* __restrict__ A, const __half* __restrict__ Wt,
    float* __restrict__ C, int N, int K, int m0, int n0, uint32_t* smu)
{
    uint32_t* Au[NSTAGE];
    uint32_t* Bu[NSTAGE];
    uint32_t asu[NSTAGE], bsu[NSTAGE];
    const uint32_t sb = cvta_smem(smu);
    #pragma unroll
    for (int s = 0; s < NSTAGE; s++) {
        Au[s] = smu + s * 2 * CH_SZ;
        Bu[s] = Au[s] + CH_SZ;
        asu[s] = sb + s * 2 * CH_SZ * 4;
        bsu[s] = asu[s] + CH_SZ * 4;
    }

    const int tid  = threadIdx.x;
    const int wid  = tid >> 5;
    const int lane = tid & 31;
    const int grp  = lane >> 2;
    const int tig  = lane & 3;
    const int m_off = (wid & 3) * 32;
    const int n_off = (wid >> 2) * 32;

    float acc[2][4][4];
    #pragma unroll
    for (int mt = 0; mt < 2; mt++)
        #pragma unroll
        for (int nt = 0; nt < 4; nt++)
            #pragma unroll
            for (int i = 0; i < 4; i++) acc[mt][nt][i] = 0.f;

    const int KT = K >> 5;
    const int am = tid >> 2;      // 0..127 row
    const int k4 = tid & 3;       // 16B group within 32-f16 chunk

    // stage(kt, buf): A 128x32 f16 (8 KB) + B 128x32 f16; 1+1 cp per thread
    #define STAGE(kt, b) do {                                               \
        const int kn_ = (kt) * 32;                                          \
        CP_ASYNC16(asu[b] + am * (R_STR * 4) + k4 * 16,                     \
                   A + (size_t)(m0 + am) * K + kn_ + k4 * 8);               \
        CP_ASYNC16(bsu[b] + am * (R_STR * 4) + k4 * 16,                     \
                   Wt + (size_t)(n0 + am) * K + kn_ + k4 * 8);              \
    } while (0)

    STAGE(0, 0); CP_COMMIT();
    STAGE(1, 1); CP_COMMIT();
    CP_WAIT1();
    __syncthreads();

    int cur = 0;   // compute buffer = kt % 3
    int stg = 2;   // stage buffer   = (kt + 2) % 3
    for (int kt = 0; kt < KT; kt++) {
        uint32_t* Ab = Au[cur];
        uint32_t* Bb = Bu[cur];

        #pragma unroll
        for (int ks = 0; ks < 2; ks++) {
            const int base = 8 * ks;
            uint32_t af[2][4], bf[4][2];
            #pragma unroll
            for (int mt = 0; mt < 2; mt++) {
                const int row = m_off + mt * 16 + grp;
                af[mt][0] = Ab[row * R_STR + base + tig];
                af[mt][1] = Ab[(row + 8) * R_STR + base + tig];
                af[mt][2] = Ab[row * R_STR + base + tig + 4];
                af[mt][3] = Ab[(row + 8) * R_STR + base + tig + 4];
            }
            #pragma unroll
            for (int nt = 0; nt < 4; nt++) {
                const int col = n_off + nt * 8 + grp;
                bf[nt][0] = Bb[col * R_STR + base + tig];
                bf[nt][1] = Bb[col * R_STR + base + tig + 4];
            }
            #pragma unroll
            for (int mt = 0; mt < 2; mt++)
                #pragma unroll
                for (int nt = 0; nt < 4; nt++)
                    mma_f16(acc[mt][nt], af[mt], bf[nt][0], bf[nt][1]);

            // Mid-chunk: stage kt+2 into buffer (kt-1)%3 (readers done last iter)
            if (ks == 0) {
                if (kt + 2 < KT) STAGE(kt + 2, stg);
                CP_COMMIT();
            }
        }

        CP_WAIT1();
        __syncthreads();

        cur = (cur == 2) ? 0 : cur + 1;
        stg = (stg == 2) ? 0 : stg + 1;
    }
    #undef STAGE

    #pragma unroll
    for (int mt = 0; mt < 2; mt++) {
        const int row = m0 + m_off + mt * 16 + grp;
        #pragma unroll
        for (int nt = 0; nt < 4; nt++) {
            const int col = n0 + n_off + nt * 8 + 2 * tig;
            *(float2*)(C + (size_t)row * N + col) =
                make_float2(acc[mt][nt][0], acc[mt][nt][1]);
            *(float2*)(C + (size_t)(row + 8) * N + col) =
                make_float2(acc[mt][nt][2], acc[mt][nt][3]);
        }
    }
}

// Fused QKV: blockIdx.x 0-7 -> Q cols, 8-9 -> K, 10-11 -> V
__global__ __launch_bounds__(512) void gemm_qkv(
    const __half* __restrict__ A, const __half* __restrict__ Wqt,
    const __half* __restrict__ Wkt, const __half* __restrict__ Wvt)
{
    extern __shared__ uint32_t smu[];
    const int ct = blockIdx.x;
    const __half* W; float* C; int N, n0;
    if (ct < 8)       { W = Wqt; C = g_Q; N = DD;       n0 = ct * 128; }
    else if (ct < 10) { W = Wkt; C = g_K; N = HKV * HD; n0 = (ct - 8) * 128; }
    else              { W = Wvt; C = g_V; N = HKV * HD; n0 = (ct - 10) * 128; }
    gemm_body_f16(A, W, C, N, DD, blockIdx.y * 128, n0, smu);
}

__global__ __launch_bounds__(512) void gemm_f16(
    const __half* __restrict__ A, const __half* __restrict__ Wt,
    float* __restrict__ C, int N, int K)
{
    extern __shared__ uint32_t smu[];
    gemm_body_f16(A, Wt, C, N, K, blockIdx.y * 128, blockIdx.x * 128, smu);
}

// ---------------------------------------------------------------------------
// RMSNorm + RoPE (unchanged; f32 in place on g_Q, g_K)
// ---------------------------------------------------------------------------
__global__ __launch_bounds__(256) void normrope_kernel(
    const float* __restrict__ rope_cos, const float* __restrict__ rope_sin,
    const float* __restrict__ q_scale, const float* __restrict__ k_scale)
{
    const int w    = blockIdx.x * 8 + (threadIdx.x >> 5);
    const int lane = threadIdx.x & 31;

    float* ptr; const float* sc; int s;
    const int NQ = NROWS * HH;
    if (w < NQ) {
        int ns = w >> 4, h = w & 15;
        ptr = g_Q + (size_t)ns * DD + h * HD;
        s = ns & (SS - 1); sc = q_scale;
    } else {
        int r = w - NQ, ns = r >> 2, hk = r & 3;
        ptr = g_K + (size_t)ns * (HKV * HD) + hk * HD;
        s = ns & (SS - 1); sc = k_scale;
    }

    float a = ptr[lane];
    float b = ptr[lane + 32];
    float ssq = a * a + b * b;
    #pragma unroll
    for (int off = 16; off > 0; off >>= 1)
        ssq += __shfl_xor_sync(0xFFFFFFFFu, ssq, off);
    float r = rsqrtf(ssq * (1.0f / 64.0f) + 1e-6f);

    float an = a * r * sc[lane];
    float bn = b * r * sc[lane + 32];
    float c  = rope_cos[s * 32 + lane];
    float sn = rope_sin[s * 32 + lane];
    ptr[lane]      = an * c - bn * sn;
    ptr[lane + 32] = bn * c + an * sn;
}

// ---------------------------------------------------------------------------
// Flash attention, f16 mma; writes f16 AO (feeds f16 out-proj GEMM).
// ---------------------------------------------------------------------------
#define QP_STR 36
#define VT_STR 132
#define ATTN_SMEM ((512 * QP_STR + 64 * VT_STR) * 4)   // 107520 B

__global__ __launch_bounds__(256) void attn_mma(
    const float* __restrict__ Q, const float* __restrict__ Kg,
    const float* __restrict__ Vg, __half* __restrict__ O)
{
    extern __shared__ uint32_t smu[];
    uint32_t* Qp = smu;
    uint32_t* Kp = smu + 256 * QP_STR;
    uint32_t* Vt = smu + 512 * QP_STR;

    const int blk = blockIdx.x;
    const int n = blk >> 4, hk = (blk >> 2) & 3, qq = blk & 3;
    const int tid = threadIdx.x, w = tid >> 5, lane = tid & 31;
    const int grp = lane >> 2, tig = lane & 3;

    #pragma unroll
    for (int i = 0; i < 16; i++) {
        int flat = tid + i * 256;
        int hrow = flat >> 4, c4 = flat & 15;
        int head = hrow >> 6, row = hrow & 63;
        float4 v = *(const float4*)(
            Q + (size_t)(n * SS + qq * 64 + row) * DD + (hk * 4 + head) * HD + c4 * 4);
        Qp[hrow * QP_STR + c4 * 2]     = pack_h2(v.x, v.y);
        Qp[hrow * QP_STR + c4 * 2 + 1] = pack_h2(v.z, v.w);
    }
    #pragma unroll
    for (int i = 0; i < 16; i++) {
        int flat = tid + i * 256;
        int row = flat >> 4, c4 = flat & 15;
        float4 v = *(const float4*)(
            Kg + (size_t)(n * SS + row) * (HKV * HD) + hk * HD + c4 * 4);
        Kp[row * QP_STR + c4 * 2]     = pack_h2(v.x, v.y);
        Kp[row * QP_STR + c4 * 2 + 1] = pack_h2(v.z, v.w);
    }
    #pragma unroll
    for (int i = 0; i < 32; i++) {
        int flat = tid + i * 256;
        int hd = flat & 63, kp = flat >> 6;
        const float* vp = Vg + (size_t)(n * SS + 2 * kp) * (HKV * HD) + hk * HD + hd;
        Vt[hd * VT_STR + kp] = pack_h2(vp[0], vp[HKV * HD]);
    }
    __syncthreads();

    const int qbase = (w >> 1) * 64 + (w & 1) * 32;
    const int qrow0 = qq * 64 + (w & 1) * 32;

    float o[2][8][4];
    #pragma unroll
    for (int mt = 0; mt < 2; mt++)
        #pragma unroll
        for (int nt = 0; nt < 8; nt++)
            #pragma unroll
            for (int e = 0; e < 4; e++) o[mt][nt][e] = 0.f;
    float m_run[2][2] = {{-1e30f,-1e30f},{-1e30f,-1e30f}};
    float l_run[2][2] = {{0.f,0.f},{0.f,0.f}};

    for (int c = 0; c < 4; c++) {
        float s[2][8][4];
        #pragma unroll
        for (int mt = 0; mt < 2; mt++)
            #pragma unroll
            for (int nt = 0; nt < 8; nt++)
                #pragma unroll
                for (int e = 0; e < 4; e++) s[mt][nt][e] = 0.f;

        #pragma unroll
        for (int ks = 0; ks < 4; ks++) {
            uint32_t a[2][4];
            #pragma unroll
            for (int mt = 0; mt < 2; mt++) {
                int r = qbase + mt * 16 + grp;
                a[mt][0] = Qp[r * QP_STR + 8 * ks + tig];
                a[mt][1] = Qp[(r + 8) * QP_STR + 8 * ks + tig];
                a[mt][2] = Qp[r * QP_STR + 8 * ks + tig + 4];
                a[mt][3] = Qp[(r + 8) * QP_STR + 8 * ks + tig + 4];
            }
            #pragma unroll
            for (int nt = 0; nt < 8; nt++) {
                int kr = c * 64 + nt * 8 + grp;
                uint32_t b0 = Kp[kr * QP_STR + 8 * ks + tig];
                uint32_t b1 = Kp[kr * QP_STR + 8 * ks + tig + 4];
                #pragma unroll
                for (int mt = 0; mt < 2; mt++) mma_f16(s[mt][nt], a[mt], b0, b1);
            }
        }

        #pragma unroll
        for (int mt = 0; mt < 2; mt++) {
            #pragma unroll
            for (int half = 0; half < 2; half++) {
                int qrow = qrow0 + mt * 16 + grp + half * 8;
                float sv[8][2];
                float mx = -1e30f;
                #pragma unroll
                for (int nt = 0; nt < 8; nt++) {
                    #pragma unroll
                    for (int e2 = 0; e2 < 2; e2++) {
                        int kcol = c * 64 + nt * 8 + 2 * tig + e2;
                        float d = s[mt][nt][half * 2 + e2] * 0.125f;
                        float ex = __expf(d * 0.04f);
                        float t = 50.f - 100.f / (ex + 1.f);
                        bool masked = (qrow < N_IMG) && (kcol >= N_IMG);
                        sv[nt][e2] = masked ? -1e30f : t;
                        mx = fmaxf(mx, sv[nt][e2]);
                    }
                }
                mx = fmaxf(mx, __shfl_xor_sync(0xFFFFFFFFu, mx, 1));
                mx = fmaxf(mx, __shfl_xor_sync(0xFFFFFFFFu, mx, 2));
                float m_new = fmaxf(m_run[mt][half], mx);
                float corr = __expf(m_run[mt][half] - m_new);
                m_run[mt][half] = m_new;
                float lsum = 0.f;
                #pragma unroll
                for (int nt = 0; nt < 8; nt++) {
                    #pragma unroll
                    for (int e2 = 0; e2 < 2; e2++) {
                        float p = __expf(sv[nt][e2] - m_new);
                        s[mt][nt][half * 2 + e2] = p;
                        lsum += p;
                    }
                }
                lsum += __shfl_xor_sync(0xFFFFFFFFu, lsum, 1);
                lsum += __shfl_xor_sync(0xFFFFFFFFu, lsum, 2);
                l_run[mt][half] = l_run[mt][half] * corr + lsum;
                #pragma unroll
                for (int nt = 0; nt < 8; nt++) {
                    o[mt][nt][half * 2]     *= corr;
                    o[mt][nt][half * 2 + 1] *= corr;
                }
            }
        }

        #pragma unroll
        for (int ks = 0; ks < 4; ks++) {
            uint32_t a[2][4];
            #pragma unroll
            for (int mt = 0; mt < 2; mt++) {
                a[mt][0] = pack_h2(s[mt][2 * ks][0],     s[mt][2 * ks][1]);
                a[mt][1] = pack_h2(s[mt][2 * ks][2],     s[mt][2 * ks][3]);
                a[mt][2] = pack_h2(s[mt][2 * ks + 1][0], s[mt][2 * ks + 1][1]);
                a[mt][3] = pack_h2(s[mt][2 * ks + 1][2], s[mt][2 * ks + 1][3]);
            }
            #pragma unroll
            for (int nt = 0; nt < 8; nt++) {
                int hd = nt * 8 + grp;
                uint32_t b0 = Vt[hd * VT_STR + c * 32 + 8 * ks + tig];
                uint32_t b1 = Vt[hd * VT_STR + c * 32 + 8 * ks + tig + 4];
                #pragma unroll
                for (int mt = 0; mt < 2; mt++) mma_f16(o[mt][nt], a[mt], b0, b1);
            }
        }
    }

    const int head = hk * 4 + (w >> 1);
    #pragma unroll
    for (int mt = 0; mt < 2; mt++) {
        int r0 = qrow0 + mt * 16 + grp;
        #pragma unroll
        for (int half = 0; half < 2; half++) {
            float inv = 1.f / l_run[mt][half];
            uint32_t* op = (uint32_t*)(O + (size_t)(n * SS + r0 + half * 8) * DD + head * HD);
            #pragma unroll
            for (int nt = 0; nt < 8; nt++)
                op[nt * 4 + tig] = pack_h2(o[mt][nt][half * 2] * inv,
                                           o[mt][nt][half * 2 + 1] * inv);
        }
    }
}

// ---------------------------------------------------------------------------
extern "C" void kernel_launch(void* const* d_in, const int* in_sizes, int n_in,
                              void* d_out, int out_size)
{
    const float* x        = (const float*)d_in[0];
    const float* rope_cos = (const float*)d_in[2];
    const float* rope_sin = (const float*)d_in[3];
    const float* Wq       = (const float*)d_in[4];
    const float* Wk       = (const float*)d_in[5];
    const float* Wv       = (const float*)d_in[6];
    const float* Wo       = (const float*)d_in[7];
    const float* q_scale  = (const float*)d_in[8];
    const float* k_scale  = (const float*)d_in[9];
    float* out = (float*)d_out;

    float *pQ, *pK, *pV;
    __half *pXh, *pAOh, *pWqt, *pWkt, *pWvt, *pWot;
    cudaGetSymbolAddress((void**)&pQ,   g_Q);
    cudaGetSymbolAddress((void**)&pK,   g_K);
    cudaGetSymbolAddress((void**)&pV,   g_V);
    cudaGetSymbolAddress((void**)&pXh,  g_Xh);
    cudaGetSymbolAddress((void**)&pAOh, g_AOh);
    cudaGetSymbolAddress((void**)&pWqt, g_Wqt);
    cudaGetSymbolAddress((void**)&pWkt, g_Wkt);
    cudaGetSymbolAddress((void**)&pWvt, g_Wvt);
    cudaGetSymbolAddress((void**)&pWot, g_Wot);

    cudaFuncSetAttribute(gemm_qkv, cudaFuncAttributeMaxDynamicSharedMemorySize, GEMM_SMEM);
    cudaFuncSetAttribute(gemm_f16, cudaFuncAttributeMaxDynamicSharedMemorySize, GEMM_SMEM);
    cudaFuncSetAttribute(attn_mma, cudaFuncAttributeMaxDynamicSharedMemorySize, ATTN_SMEM);

    // 0) Convert x -> f16; convert+transpose weights -> f16 [N][K]
    f32_to_f16_kernel<<<(NROWS * DD / 4 + 255) / 256, 256>>>(
        (const float4*)x, (uint2*)pXh, NROWS * DD / 4);
    dim3 tb(32, 8);
    transpose_f16_kernel<<<dim3(DD / 32, DD / 32), tb>>>(Wq, pWqt, DD, DD);
    transpose_f16_kernel<<<dim3((HKV * HD) / 32, DD / 32), tb>>>(Wk, pWkt, DD, HKV * HD);
    transpose_f16_kernel<<<dim3((HKV * HD) / 32, DD / 32), tb>>>(Wv, pWvt, DD, HKV * HD);
    transpose_f16_kernel<<<dim3(DD / 32, DD / 32), tb>>>(Wo, pWot, DD, DD);

    // 1) Fused Q/K/V projections (f16 mma)
    gemm_qkv<<<dim3(12, NROWS / 128), 512, GEMM_SMEM>>>(pXh, pWqt, pWkt, pWvt);

    // 2) RMSNorm + RoPE
    normrope_kernel<<<(NROWS * HH + NROWS * HKV) / 8, 256>>>(rope_cos, rope_sin,
                                                             q_scale, k_scale);

    // 3) Flash attention (f16 mma); writes f16 AO
    attn_mma<<<NSEQ * HKV * 4, 256, ATTN_SMEM>>>(pQ, pK, pV, pAOh);

    // 4) Output projection (f16 mma)
    gemm_f16<<<dim3(DD / 128, NROWS / 128), 512, GEMM_SMEM>>>(pAOh, pWot, out, DD, DD);
}